// round 2
// baseline (speedup 1.0000x reference)
#include <cuda_runtime.h>
#include <math.h>

#define NB 16
#define NA 2048
#define ND 512
#define NR 10
#define INV_SQRT_DK 0.04419417382415922f  // 1/sqrt(512)

// Scratch (no device allocations allowed)
__device__ float g_left[(size_t)NB * NA * NR];    // left projection, pre-scaled by 1/sqrt(dk)
__device__ float g_rightT[(size_t)NB * NA * NR];  // right projection, [b][c][r]
__device__ float g_offs[(size_t)NB * NA];         // per-query softmax offset: m + ln(l)

// ---------------------------------------------------------------------------
// K1: left[b,a,r] = (x[b,a,:] . W1[:,r]) * inv_sqrt_dk
//     rightT[b,c,r] = W2[r,:] . x[b,c,:]
// One warp per row of x; W1 (transposed) and W2 staged in smem.
// ---------------------------------------------------------------------------
__global__ void k1_proj(const float* __restrict__ x,
                        const float* __restrict__ W1,
                        const float* __restrict__ W2) {
    __shared__ float W1T[NR][ND];
    __shared__ float W2s[NR][ND];
    int tid = threadIdx.x;
    for (int idx = tid; idx < ND * NR; idx += blockDim.x) {
        int d = idx / NR, r = idx % NR;       // W1 is [D, R], r fastest
        W1T[r][d] = W1[idx];
    }
    for (int idx = tid; idx < NR * ND; idx += blockDim.x) {
        W2s[idx / ND][idx % ND] = W2[idx];    // W2 is [R, D], d fastest
    }
    __syncthreads();

    int warp = tid >> 5, lane = tid & 31;
    int row = blockIdx.x * 8 + warp;          // global row in [0, B*A)
    const float* xr = x + (size_t)row * ND;

    float accL[NR], accR[NR];
#pragma unroll
    for (int r = 0; r < NR; r++) { accL[r] = 0.f; accR[r] = 0.f; }

#pragma unroll
    for (int k = 0; k < ND / 32; k++) {
        int d = lane + 32 * k;
        float xv = xr[d];
#pragma unroll
        for (int r = 0; r < NR; r++) {
            accL[r] += xv * W1T[r][d];
            accR[r] += xv * W2s[r][d];
        }
    }
#pragma unroll
    for (int r = 0; r < NR; r++) {
#pragma unroll
        for (int off = 16; off; off >>= 1) {
            accL[r] += __shfl_down_sync(0xffffffffu, accL[r], off);
            accR[r] += __shfl_down_sync(0xffffffffu, accR[r], off);
        }
    }
    if (lane == 0) {
        float* lp = g_left  + (size_t)row * NR;
        float* rp = g_rightT + (size_t)row * NR;
#pragma unroll
        for (int r = 0; r < NR; r++) {
            lp[r] = accL[r] * INV_SQRT_DK;
            rp[r] = accR[r];
        }
    }
}

// ---------------------------------------------------------------------------
// K2: per query row a (within batch b):
//   s_c = left_a . rightT_c   (already includes 1/sqrt(dk))
//   m = max_c s_c ; l = sum_c exp(s_c - m) ; offs = m + ln(l)
// ---------------------------------------------------------------------------
#define K2_TA 32
#define K2_CT 256
__global__ void k2_stats() {
    int b = blockIdx.y;
    int a0 = blockIdx.x * K2_TA;
    __shared__ float Ls[K2_TA][NR];
    __shared__ float Rts[K2_CT][NR];
    int tid = threadIdx.x;

    for (int idx = tid; idx < K2_TA * NR; idx += 256) {
        int rr = idx / NR, r = idx % NR;
        Ls[rr][r] = g_left[((size_t)b * NA + a0 + rr) * NR + r];
    }

    int rloc = tid >> 3;   // 0..31 : row within tile
    int sub  = tid & 7;    // 0..7  : c-slice within row

    float m = -1e30f, l = 0.f;

    for (int c0 = 0; c0 < NA; c0 += K2_CT) {
        __syncthreads();
        for (int idx = tid; idx < K2_CT * NR; idx += 256) {
            int cc = idx / NR, r = idx % NR;
            Rts[cc][r] = g_rightT[((size_t)b * NA + c0 + cc) * NR + r];
        }
        __syncthreads();
        for (int c = sub; c < K2_CT; c += 8) {
            float s = 0.f;
#pragma unroll
            for (int r = 0; r < NR; r++) s += Ls[rloc][r] * Rts[c][r];
            float nm = fmaxf(m, s);
            l = l * __expf(m - nm) + __expf(s - nm);
            m = nm;
        }
    }
    // combine the 8 partial (m,l) per row (lanes sub=0..7 are adjacent)
#pragma unroll
    for (int off = 4; off; off >>= 1) {
        float m2 = __shfl_xor_sync(0xffffffffu, m, off);
        float l2 = __shfl_xor_sync(0xffffffffu, l, off);
        float nm = fmaxf(m, m2);
        l = l * __expf(m - nm) + l2 * __expf(m2 - nm);
        m = nm;
    }
    if (sub == 0) g_offs[(size_t)b * NA + a0 + rloc] = m + logf(l);
}

// ---------------------------------------------------------------------------
// K3: out[b, a0:a0+64, d0:d0+128] = sum_c exp(s - offs) * x[b, c, d0:d0+128]
// P tile (64x32) regenerated on the fly from rank-10 factors each c-tile.
// Register tiling: 256 threads, each owns a 4x8 micro-tile.
// ---------------------------------------------------------------------------
#define BM 64
#define BN 32
#define BD 128
__global__ void __launch_bounds__(256, 2)
k3_attn_out(const float* __restrict__ x, float* __restrict__ out) {
    int b  = blockIdx.z;
    int a0 = blockIdx.x * BM;
    int d0 = blockIdx.y * BD;

    __shared__ float Ls[BM][NR];
    __shared__ float os[BM];
    __shared__ float Rts[BN][NR + 1];   // pad -> stride 11, conflict-free
    __shared__ float xs[BN][BD];
    __shared__ float ws[BM][BN + 1];    // pad -> stride 33, conflict-free

    int tid = threadIdx.x;
    int ty = tid >> 4;     // 0..15
    int tx = tid & 15;     // 0..15

    for (int idx = tid; idx < BM * NR; idx += 256) {
        int rr = idx / NR, r = idx % NR;
        Ls[rr][r] = g_left[((size_t)b * NA + a0 + rr) * NR + r];
    }
    if (tid < BM) os[tid] = g_offs[(size_t)b * NA + a0 + tid];

    float acc[4][8];
#pragma unroll
    for (int i = 0; i < 4; i++)
#pragma unroll
        for (int j = 0; j < 8; j++) acc[i][j] = 0.f;

    const float* xb = x + (size_t)b * NA * ND;

    for (int c0 = 0; c0 < NA; c0 += BN) {
        // stage rightT tile (320 floats) — grid-stride: 320 > 256 threads!
        for (int idx = tid; idx < BN * NR; idx += 256) {
            int cc = idx / NR, r = idx % NR;
            Rts[cc][r] = g_rightT[((size_t)b * NA + c0 + cc) * NR + r];
        }
        // stage x tile [32 x 128] via float4 (1024 float4 units / 256 threads)
#pragma unroll
        for (int it = 0; it < 4; it++) {
            int idx = tid + 256 * it;
            int row = idx >> 5;           // 32 float4 per row
            int c4  = idx & 31;
            *(float4*)&xs[row][c4 * 4] =
                *(const float4*)&xb[(size_t)(c0 + row) * ND + d0 + c4 * 4];
        }
        __syncthreads();

        // regenerate P tile: ws[row][col] = exp(L_row . Rt_col - offs_row)
#pragma unroll
        for (int j = 0; j < 8; j++) {
            int idx = tid + 256 * j;
            int row = idx >> 5, col = idx & 31;
            float s = 0.f;
#pragma unroll
            for (int r = 0; r < NR; r++) s += Ls[row][r] * Rts[col][r];
            ws[row][col] = __expf(s - os[row]);
        }
        __syncthreads();

        // acc += ws[64x32] @ xs[32x128]
#pragma unroll
        for (int kk = 0; kk < BN; kk++) {
            float af[4], bf[8];
#pragma unroll
            for (int ii = 0; ii < 4; ii++) af[ii] = ws[ty + 16 * ii][kk];
#pragma unroll
            for (int jj = 0; jj < 8; jj++) bf[jj] = xs[kk][tx + 16 * jj];
#pragma unroll
            for (int ii = 0; ii < 4; ii++)
#pragma unroll
                for (int jj = 0; jj < 8; jj++)
                    acc[ii][jj] += af[ii] * bf[jj];
        }
        __syncthreads();
    }

#pragma unroll
    for (int ii = 0; ii < 4; ii++) {
        int a = a0 + ty + 16 * ii;
        float* op = out + ((size_t)b * NA + a) * ND + d0;
#pragma unroll
        for (int jj = 0; jj < 8; jj++)
            op[tx + 16 * jj] = acc[ii][jj];
    }
}

// ---------------------------------------------------------------------------
extern "C" void kernel_launch(void* const* d_in, const int* in_sizes, int n_in,
                              void* d_out, int out_size) {
    const float* x  = (const float*)d_in[0];
    const float* W1 = (const float*)d_in[1];
    const float* W2 = (const float*)d_in[2];
    float* out = (float*)d_out;

    k1_proj<<<(NB * NA) / 8, 256>>>(x, W1, W2);
    k2_stats<<<dim3(NA / K2_TA, NB), 256>>>();
    k3_attn_out<<<dim3(NA / BM, ND / BD, NB), 256>>>(x, out);
}

// round 4
// speedup vs baseline: 2.9921x; 2.9921x over previous
#include <cuda_runtime.h>
#include <cstdint>
#include <math.h>

#define NB 16
#define NA 2048
#define ND 512
#define NR 10
#define INV_SQRT_DK 0.04419417382415922f  // 1/sqrt(512)

// Scratch (no device allocations allowed)
__device__ float g_left[(size_t)NB * NA * NR];    // left proj, pre-scaled by 1/sqrt(dk)
__device__ float g_rightT[(size_t)NB * NA * NR];  // right proj, [b][c][r]

__device__ __forceinline__ uint32_t f2tf32(float f) {
    uint32_t u;
    asm("cvt.rna.tf32.f32 %0, %1;" : "=r"(u) : "f"(f));
    return u;
}

__device__ __forceinline__ void mma_tf32(float* d, const uint32_t* a, const uint32_t* bfr) {
    asm volatile(
        "mma.sync.aligned.m16n8k8.row.col.f32.tf32.tf32.f32 "
        "{%0,%1,%2,%3}, {%4,%5,%6,%7}, {%8,%9}, {%0,%1,%2,%3};"
        : "+f"(d[0]), "+f"(d[1]), "+f"(d[2]), "+f"(d[3])
        : "r"(a[0]), "r"(a[1]), "r"(a[2]), "r"(a[3]), "r"(bfr[0]), "r"(bfr[1]));
}

// ===========================================================================
// K1: projections. 4 rows per warp to amortize W smem reads.
// ===========================================================================
__global__ void __launch_bounds__(256)
k1_proj(const float* __restrict__ x, const float* __restrict__ W1,
        const float* __restrict__ W2) {
    __shared__ float W1T[NR][ND];
    __shared__ float W2s[NR][ND];
    int tid = threadIdx.x;
    for (int idx = tid; idx < ND * NR; idx += 256) {
        int d = idx / NR, r = idx % NR;
        W1T[r][d] = W1[idx];               // W1 [D, R], r fastest
    }
    for (int idx = tid; idx < NR * ND; idx += 256) {
        W2s[idx / ND][idx % ND] = W2[idx]; // W2 [R, D], d fastest
    }
    __syncthreads();

    int warp = tid >> 5, lane = tid & 31;
    int row0 = blockIdx.x * 32 + warp * 4;
    const float* xr0 = x + (size_t)row0 * ND;

    float accL[4][NR], accR[4][NR];
#pragma unroll
    for (int i = 0; i < 4; i++)
#pragma unroll
        for (int r = 0; r < NR; r++) { accL[i][r] = 0.f; accR[i][r] = 0.f; }

#pragma unroll
    for (int k = 0; k < ND / 32; k++) {
        int d = lane + 32 * k;
        float xv[4];
#pragma unroll
        for (int i = 0; i < 4; i++) xv[i] = xr0[(size_t)i * ND + d];
#pragma unroll
        for (int r = 0; r < NR; r++) {
            float w1 = W1T[r][d];
            float w2 = W2s[r][d];
#pragma unroll
            for (int i = 0; i < 4; i++) {
                accL[i][r] += xv[i] * w1;
                accR[i][r] += xv[i] * w2;
            }
        }
    }
#pragma unroll
    for (int i = 0; i < 4; i++)
#pragma unroll
        for (int r = 0; r < NR; r++) {
#pragma unroll
            for (int off = 16; off; off >>= 1) {
                accL[i][r] += __shfl_down_sync(0xffffffffu, accL[i][r], off);
                accR[i][r] += __shfl_down_sync(0xffffffffu, accR[i][r], off);
            }
        }
    if (lane == 0) {
#pragma unroll
        for (int i = 0; i < 4; i++) {
            float* lp = g_left   + (size_t)(row0 + i) * NR;
            float* rp = g_rightT + (size_t)(row0 + i) * NR;
#pragma unroll
            for (int r = 0; r < NR; r++) {
                lp[r] = accL[i][r] * INV_SQRT_DK;
                rp[r] = accR[i][r];
            }
        }
    }
}

// ===========================================================================
// K3: warp-MMA (tf32 mma.sync) attention-weighted sum.
//   CTA tile: M=128 queries x N=128 d-cols. K-loop over 2048 keys, KC=32.
//   A tile: P' = exp(score) tf32 [128 x 32], smem stride 36 (conflict-free frags)
//   B tile: x tf32 [32 k x 128 n], smem stride 136 (conflict-free frags)
//   8 warps: 2(m) x 4(n), each warp 64x32 output via m16n8k8.
//   Unnormalized accumulation; per-row softmax denominator in regs -> epilogue.
// ===========================================================================
#define KC 32
#define NCHUNK (NA / KC)

__global__ void __launch_bounds__(256, 2)
k3_attn_mma(const float* __restrict__ x, float* __restrict__ out) {
    __shared__ uint32_t As[128][36];
    __shared__ uint32_t Bs[KC][136];
    __shared__ float RtT[NR][32];
    __shared__ float sl[128];

    int tid = threadIdx.x;
    int wid = tid >> 5, lane = tid & 31;
    int b  = blockIdx.z;
    int a0 = blockIdx.x * 128;
    int n0 = blockIdx.y * 128;

    // ---- score-gen mapping: 2 rows x 8 k per thread ----
    int mg = tid >> 2;       // 0..63 -> rows 2mg, 2mg+1
    int kg = tid & 3;        // 0..3  -> k cols 8kg..8kg+7
    float ls[2][NR];
#pragma unroll
    for (int i = 0; i < 2; i++) {
        const float* lp = g_left + ((size_t)b * NA + a0 + 2 * mg + i) * NR;
#pragma unroll
        for (int r = 0; r < NR; r++) ls[i][r] = lp[r];
    }
    float lacc[2] = {0.f, 0.f};

    // ---- MMA mapping ----
    int wm = wid >> 2, wn = wid & 3;  // warp tile: rows wm*64.., cols wn*32..
    float acc[4][4][4];
#pragma unroll
    for (int mt = 0; mt < 4; mt++)
#pragma unroll
        for (int nt = 0; nt < 4; nt++)
#pragma unroll
            for (int q = 0; q < 4; q++) acc[mt][nt][q] = 0.f;

    const float* xb = x + (size_t)b * NA * ND;

    for (int c = 0; c < NCHUNK; c++) {
        int c0 = c * KC;
        __syncthreads();  // previous chunk fully consumed

        // ---- stage RtT [r][k] ----
        for (int idx = tid; idx < KC * NR; idx += 256) {
            int k = idx / NR, r = idx % NR;
            RtT[r][k] = g_rightT[((size_t)b * NA + c0 + k) * NR + r];
        }

        // ---- stage B tile: x[c0+k][n0+n] -> tf32 ----
#pragma unroll
        for (int it = 0; it < 4; it++) {
            int u = tid + 256 * it;     // < 1024 float4 units
            int kk = u >> 5;            // 0..31
            int f4 = u & 31;            // 0..31 -> n = 4*f4
            float4 v = *(const float4*)&xb[(size_t)(c0 + kk) * ND + n0 + 4 * f4];
            uint4 t;
            t.x = f2tf32(v.x); t.y = f2tf32(v.y); t.z = f2tf32(v.z); t.w = f2tf32(v.w);
            *(uint4*)&Bs[kk][4 * f4] = t;
        }
        __syncthreads();  // RtT ready

        // ---- stage A tile: P' = exp(score) ----
        {
            float sc[2][8];
#pragma unroll
            for (int i = 0; i < 2; i++)
#pragma unroll
                for (int j = 0; j < 8; j++) sc[i][j] = 0.f;
#pragma unroll
            for (int r = 0; r < NR; r++) {
                float4 rt0 = *(const float4*)&RtT[r][8 * kg];
                float4 rt1 = *(const float4*)&RtT[r][8 * kg + 4];
#pragma unroll
                for (int i = 0; i < 2; i++) {
                    float lv = ls[i][r];
                    sc[i][0] += lv * rt0.x; sc[i][1] += lv * rt0.y;
                    sc[i][2] += lv * rt0.z; sc[i][3] += lv * rt0.w;
                    sc[i][4] += lv * rt1.x; sc[i][5] += lv * rt1.y;
                    sc[i][6] += lv * rt1.z; sc[i][7] += lv * rt1.w;
                }
            }
#pragma unroll
            for (int i = 0; i < 2; i++) {
                int m = 2 * mg + i;
                uint4 t0, t1;
                float e;
                float s = 0.f;
                e = __expf(sc[i][0]); t0.x = f2tf32(e); s += __uint_as_float(t0.x);
                e = __expf(sc[i][1]); t0.y = f2tf32(e); s += __uint_as_float(t0.y);
                e = __expf(sc[i][2]); t0.z = f2tf32(e); s += __uint_as_float(t0.z);
                e = __expf(sc[i][3]); t0.w = f2tf32(e); s += __uint_as_float(t0.w);
                e = __expf(sc[i][4]); t1.x = f2tf32(e); s += __uint_as_float(t1.x);
                e = __expf(sc[i][5]); t1.y = f2tf32(e); s += __uint_as_float(t1.y);
                e = __expf(sc[i][6]); t1.z = f2tf32(e); s += __uint_as_float(t1.z);
                e = __expf(sc[i][7]); t1.w = f2tf32(e); s += __uint_as_float(t1.w);
                lacc[i] += s;
                *(uint4*)&As[m][8 * kg]     = t0;
                *(uint4*)&As[m][8 * kg + 4] = t1;
            }
        }
        __syncthreads();  // A, B staged

        // ---- warp MMAs: 4 k-steps x 4 m-subtiles x 4 n-subtiles ----
#pragma unroll
        for (int ks = 0; ks < 4; ks++) {
            uint32_t afr[4][4], bfr[4][2];
            int arow = wm * 64 + (lane >> 2);
            int acol = ks * 8 + (lane & 3);
#pragma unroll
            for (int mt = 0; mt < 4; mt++) {
                afr[mt][0] = As[arow + mt * 16][acol];
                afr[mt][1] = As[arow + mt * 16 + 8][acol];
                afr[mt][2] = As[arow + mt * 16][acol + 4];
                afr[mt][3] = As[arow + mt * 16 + 8][acol + 4];
            }
            int brow = ks * 8 + (lane & 3);
            int bcol = wn * 32 + (lane >> 2);
#pragma unroll
            for (int nt = 0; nt < 4; nt++) {
                bfr[nt][0] = Bs[brow][bcol + nt * 8];
                bfr[nt][1] = Bs[brow + 4][bcol + nt * 8];
            }
#pragma unroll
            for (int mt = 0; mt < 4; mt++)
#pragma unroll
                for (int nt = 0; nt < 4; nt++)
                    mma_tf32(acc[mt][nt], afr[mt], bfr[nt]);
        }
    }

    // ---- softmax denominators: reduce lacc over the 4 kg threads ----
#pragma unroll
    for (int off = 1; off < 4; off <<= 1)
#pragma unroll
        for (int i = 0; i < 2; i++)
            lacc[i] += __shfl_xor_sync(0xffffffffu, lacc[i], off);
    if (kg == 0) {
#pragma unroll
        for (int i = 0; i < 2; i++) sl[2 * mg + i] = lacc[i];
    }
    __syncthreads();

    // ---- epilogue: normalize + store ----
#pragma unroll
    for (int mt = 0; mt < 4; mt++) {
        int r0 = wm * 64 + mt * 16 + (lane >> 2);
        int r1 = r0 + 8;
        float inv0 = 1.0f / sl[r0];
        float inv1 = 1.0f / sl[r1];
        float* op0 = out + ((size_t)b * NA + a0 + r0) * ND + n0;
        float* op1 = out + ((size_t)b * NA + a0 + r1) * ND + n0;
#pragma unroll
        for (int nt = 0; nt < 4; nt++) {
            int col = wn * 32 + nt * 8 + 2 * (lane & 3);
            float2 v0 = make_float2(acc[mt][nt][0] * inv0, acc[mt][nt][1] * inv0);
            float2 v1 = make_float2(acc[mt][nt][2] * inv1, acc[mt][nt][3] * inv1);
            *(float2*)&op0[col] = v0;
            *(float2*)&op1[col] = v1;
        }
    }
}

// ---------------------------------------------------------------------------
extern "C" void kernel_launch(void* const* d_in, const int* in_sizes, int n_in,
                              void* d_out, int out_size) {
    const float* x  = (const float*)d_in[0];
    const float* W1 = (const float*)d_in[1];
    const float* W2 = (const float*)d_in[2];
    float* out = (float*)d_out;

    k1_proj<<<(NB * NA) / 32, 256>>>(x, W1, W2);
    k3_attn_mma<<<dim3(NA / 128, ND / 128, NB), 256>>>(x, out);
}

// round 5
// speedup vs baseline: 3.2564x; 1.0883x over previous
#include <cuda_runtime.h>
#include <cstdint>
#include <math.h>

#define NB 16
#define NA 2048
#define ND 512
#define NR 10
#define INV_SQRT_DK 0.04419417382415922f  // 1/sqrt(512)

// Scratch (no device allocations allowed)
__device__ float g_left[(size_t)NB * NA * NR];    // left proj, pre-scaled by 1/sqrt(dk)
__device__ float g_rightT[(size_t)NB * NA * NR];  // right proj, [b][c][r]

__device__ __forceinline__ uint32_t f2tf32(float f) {
    uint32_t u;
    asm("cvt.rna.tf32.f32 %0, %1;" : "=r"(u) : "f"(f));
    return u;
}
__device__ __forceinline__ uint32_t smem_u32(const void* p) {
    uint32_t a;
    asm("{ .reg .u64 t; cvta.to.shared.u64 t, %1; cvt.u32.u64 %0, t; }" : "=r"(a) : "l"(p));
    return a;
}
__device__ __forceinline__ void cp_async16(uint32_t saddr, const void* gptr) {
    asm volatile("cp.async.cg.shared.global [%0], [%1], 16;" :: "r"(saddr), "l"(gptr) : "memory");
}
#define CP_COMMIT() asm volatile("cp.async.commit_group;" ::: "memory")
#define CP_WAIT1()  asm volatile("cp.async.wait_group 1;" ::: "memory")

__device__ __forceinline__ void mma_tf32(float* d, const uint32_t* a, const uint32_t* bfr) {
    asm volatile(
        "mma.sync.aligned.m16n8k8.row.col.f32.tf32.tf32.f32 "
        "{%0,%1,%2,%3}, {%4,%5,%6,%7}, {%8,%9}, {%0,%1,%2,%3};"
        : "+f"(d[0]), "+f"(d[1]), "+f"(d[2]), "+f"(d[3])
        : "r"(a[0]), "r"(a[1]), "r"(a[2]), "r"(a[3]), "r"(bfr[0]), "r"(bfr[1]));
}

// ===========================================================================
// K1: projections. 4 rows per warp to amortize W smem reads.
// ===========================================================================
__global__ void __launch_bounds__(256)
k1_proj(const float* __restrict__ x, const float* __restrict__ W1,
        const float* __restrict__ W2) {
    __shared__ float W1T[NR][ND];
    __shared__ float W2s[NR][ND];
    int tid = threadIdx.x;
    for (int idx = tid; idx < ND * NR; idx += 256) {
        int d = idx / NR, r = idx % NR;
        W1T[r][d] = W1[idx];               // W1 [D, R], r fastest
    }
    for (int idx = tid; idx < NR * ND; idx += 256) {
        W2s[idx / ND][idx % ND] = W2[idx]; // W2 [R, D], d fastest
    }
    __syncthreads();

    int warp = tid >> 5, lane = tid & 31;
    int row0 = blockIdx.x * 32 + warp * 4;
    const float* xr0 = x + (size_t)row0 * ND;

    float accL[4][NR], accR[4][NR];
#pragma unroll
    for (int i = 0; i < 4; i++)
#pragma unroll
        for (int r = 0; r < NR; r++) { accL[i][r] = 0.f; accR[i][r] = 0.f; }

#pragma unroll
    for (int k = 0; k < ND / 32; k++) {
        int d = lane + 32 * k;
        float xv[4];
#pragma unroll
        for (int i = 0; i < 4; i++) xv[i] = xr0[(size_t)i * ND + d];
#pragma unroll
        for (int r = 0; r < NR; r++) {
            float w1 = W1T[r][d];
            float w2 = W2s[r][d];
#pragma unroll
            for (int i = 0; i < 4; i++) {
                accL[i][r] += xv[i] * w1;
                accR[i][r] += xv[i] * w2;
            }
        }
    }
#pragma unroll
    for (int i = 0; i < 4; i++)
#pragma unroll
        for (int r = 0; r < NR; r++) {
#pragma unroll
            for (int off = 16; off; off >>= 1) {
                accL[i][r] += __shfl_down_sync(0xffffffffu, accL[i][r], off);
                accR[i][r] += __shfl_down_sync(0xffffffffu, accR[i][r], off);
            }
        }
    if (lane == 0) {
#pragma unroll
        for (int i = 0; i < 4; i++) {
            float* lp = g_left   + (size_t)(row0 + i) * NR;
            float* rp = g_rightT + (size_t)(row0 + i) * NR;
#pragma unroll
            for (int r = 0; r < NR; r++) {
                lp[r] = accL[i][r] * INV_SQRT_DK;
                rp[r] = accR[i][r];
            }
        }
    }
}

// ===========================================================================
// K3: warp-MMA tf32 attention-weighted sum, cp.async pipelined.
//   CTA: M=128 x N=128, K-loop 2048 keys, KC=32.
//   A: exp-scores tf32, PAIR-PACKED [m][40] (word p=8g+2s+hi <-> k=8g+4hi+s)
//      -> conflict-free LDS.64 fragment loads.
//   B: raw fp32 x staged by cp.async, [k][136], triple-buffered (mma.tf32
//      truncates mantissa -> implicit RTZ tf32, unbiased on symmetric x).
//   RtT: rank-10 right factors, double-buffered, prefetched 1 chunk ahead.
//   2 barriers per chunk. Unnormalized accumulation; epilogue divide.
// ===========================================================================
#define KC 32
#define NCHUNK (NA / KC)
// dynamic smem layout (bytes)
#define OFF_AS 0
#define OFF_BS 20480
#define OFF_RT 72704
#define OFF_SL 75264
#define SMEM_K3 75776

__global__ void __launch_bounds__(256, 2)
k3_attn_mma(const float* __restrict__ x, float* __restrict__ out) {
    extern __shared__ char smem[];
    uint32_t* As  = (uint32_t*)(smem + OFF_AS);   // [128][40]
    float*    Bs  = (float*)(smem + OFF_BS);      // [3][32][136]
    float*    RtT = (float*)(smem + OFF_RT);      // [2][10][32]
    float*    sl  = (float*)(smem + OFF_SL);      // [128]
    uint32_t  sb  = smem_u32(smem);

    int tid = threadIdx.x;
    int wid = tid >> 5, lane = tid & 31;
    int b  = blockIdx.z;
    int a0 = blockIdx.x * 128;
    int n0 = blockIdx.y * 128;

    // score-gen mapping: 2 rows x 8 k per thread
    int mg = tid >> 2, kg = tid & 3;
    float ls[2][NR];
#pragma unroll
    for (int i = 0; i < 2; i++) {
        const float* lp = g_left + ((size_t)b * NA + a0 + 2 * mg + i) * NR;
#pragma unroll
        for (int r = 0; r < NR; r++) ls[i][r] = lp[r];
    }
    float lacc[2] = {0.f, 0.f};

    // MMA mapping
    int wm = wid >> 2, wn = wid & 3;
    int fs = lane & 3, fq = lane >> 2;
    float acc[4][4][4];
#pragma unroll
    for (int mt = 0; mt < 4; mt++)
#pragma unroll
        for (int nt = 0; nt < 4; nt++)
#pragma unroll
            for (int q = 0; q < 4; q++) acc[mt][nt][q] = 0.f;

    const float* xb = x + (size_t)b * NA * ND;

    // ---- prologue: prefetch B[0], B[1], RtT[0] ----
#pragma unroll
    for (int pc = 0; pc < 2; pc++) {
#pragma unroll
        for (int it = 0; it < 4; it++) {
            int u = tid + 256 * it;
            int kk = u >> 5, f4 = u & 31;
            uint32_t dst = sb + OFF_BS + (uint32_t)(pc * (KC * 136) + kk * 136 + 4 * f4) * 4;
            cp_async16(dst, xb + (size_t)(pc * KC + kk) * ND + n0 + 4 * f4);
        }
        CP_COMMIT();
    }
    for (int idx = tid; idx < KC * NR; idx += 256) {
        int k = idx / NR, r = idx % NR;
        RtT[r * 32 + k] = g_rightT[((size_t)b * NA + k) * NR + r];
    }

    for (int c = 0; c < NCHUNK; c++) {
        int buf = c % 3;
        CP_WAIT1();        // B[c] landed
        __syncthreads();   // visible to all; also: all warps done with MMA(c-1)

        // prefetch B[c+2] into the buffer MMA(c-1) just released
        if (c + 2 < NCHUNK) {
            int pb = (c + 2) % 3;
#pragma unroll
            for (int it = 0; it < 4; it++) {
                int u = tid + 256 * it;
                int kk = u >> 5, f4 = u & 31;
                uint32_t dst = sb + OFF_BS + (uint32_t)(pb * (KC * 136) + kk * 136 + 4 * f4) * 4;
                cp_async16(dst, xb + (size_t)((c + 2) * KC + kk) * ND + n0 + 4 * f4);
            }
        }
        CP_COMMIT();       // one group per iter (may be empty) keeps wait_group math fixed

        // prefetch RtT for chunk c+1 (other buffer; no barrier needed)
        if (c + 1 < NCHUNK) {
            float* rtw = RtT + ((c + 1) & 1) * (NR * 32);
            int c1 = (c + 1) * KC;
            for (int idx = tid; idx < KC * NR; idx += 256) {
                int k = idx / NR, r = idx % NR;
                rtw[r * 32 + k] = g_rightT[((size_t)b * NA + c1 + k) * NR + r];
            }
        }

        // ---- score-gen: P' = exp(score), pair-packed into As ----
        {
            const float* rt = RtT + (c & 1) * (NR * 32);
            float sc[2][8];
#pragma unroll
            for (int i = 0; i < 2; i++)
#pragma unroll
                for (int j = 0; j < 8; j++) sc[i][j] = 0.f;
#pragma unroll
            for (int r = 0; r < NR; r++) {
                float4 rt0 = *(const float4*)&rt[r * 32 + 8 * kg];
                float4 rt1 = *(const float4*)&rt[r * 32 + 8 * kg + 4];
#pragma unroll
                for (int i = 0; i < 2; i++) {
                    float lv = ls[i][r];
                    sc[i][0] += lv * rt0.x; sc[i][1] += lv * rt0.y;
                    sc[i][2] += lv * rt0.z; sc[i][3] += lv * rt0.w;
                    sc[i][4] += lv * rt1.x; sc[i][5] += lv * rt1.y;
                    sc[i][6] += lv * rt1.z; sc[i][7] += lv * rt1.w;
                }
            }
#pragma unroll
            for (int i = 0; i < 2; i++) {
                float e[8];
                float s = 0.f;
#pragma unroll
                for (int j = 0; j < 8; j++) {
                    float ev = __expf(sc[i][j]);
                    uint32_t t = f2tf32(ev);
                    e[j] = __uint_as_float(t);   // keep exactly what the MMA sees
                    s += e[j];
                }
                lacc[i] += s;
                int m = 2 * mg + i;
                // packed order: word j=2s+hi <-> k=4hi+s (within this thread's 8 k)
                uint4 t0, t1;
                t0.x = __float_as_uint(e[0]); t0.y = __float_as_uint(e[4]);
                t0.z = __float_as_uint(e[1]); t0.w = __float_as_uint(e[5]);
                t1.x = __float_as_uint(e[2]); t1.y = __float_as_uint(e[6]);
                t1.z = __float_as_uint(e[3]); t1.w = __float_as_uint(e[7]);
                *(uint4*)&As[m * 40 + 8 * kg]     = t0;
                *(uint4*)&As[m * 40 + 8 * kg + 4] = t1;
            }
        }
        __syncthreads();   // A staged

        // ---- MMAs: A via LDS.64 pairs, B scalar (conflict-free) ----
        const uint2* Ap = (const uint2*)As;            // stride 20 uint2
        const float* Bb = Bs + buf * (KC * 136);
#pragma unroll
        for (int ks = 0; ks < 4; ks++) {
            uint32_t afr[4][4], bfr[4][2];
            int arow = wm * 64 + fq;
#pragma unroll
            for (int mt = 0; mt < 4; mt++) {
                uint2 lo = Ap[(arow + mt * 16) * 20 + 4 * ks + fs];
                uint2 hi = Ap[(arow + mt * 16 + 8) * 20 + 4 * ks + fs];
                afr[mt][0] = lo.x; afr[mt][1] = hi.x;
                afr[mt][2] = lo.y; afr[mt][3] = hi.y;
            }
            int brow = ks * 8 + fs;
            int bcol = wn * 32 + fq;
#pragma unroll
            for (int nt = 0; nt < 4; nt++) {
                bfr[nt][0] = __float_as_uint(Bb[brow * 136 + bcol + nt * 8]);
                bfr[nt][1] = __float_as_uint(Bb[(brow + 4) * 136 + bcol + nt * 8]);
            }
#pragma unroll
            for (int mt = 0; mt < 4; mt++)
#pragma unroll
                for (int nt = 0; nt < 4; nt++)
                    mma_tf32(acc[mt][nt], afr[mt], bfr[nt]);
        }
    }

    // ---- softmax denominators ----
#pragma unroll
    for (int off = 1; off < 4; off <<= 1)
#pragma unroll
        for (int i = 0; i < 2; i++)
            lacc[i] += __shfl_xor_sync(0xffffffffu, lacc[i], off);
    if (kg == 0) {
#pragma unroll
        for (int i = 0; i < 2; i++) sl[2 * mg + i] = lacc[i];
    }
    __syncthreads();

    // ---- epilogue: normalize + store ----
#pragma unroll
    for (int mt = 0; mt < 4; mt++) {
        int r0 = wm * 64 + mt * 16 + fq;
        int r1 = r0 + 8;
        float inv0 = 1.0f / sl[r0];
        float inv1 = 1.0f / sl[r1];
        float* op0 = out + ((size_t)b * NA + a0 + r0) * ND + n0;
        float* op1 = out + ((size_t)b * NA + a0 + r1) * ND + n0;
#pragma unroll
        for (int nt = 0; nt < 4; nt++) {
            int col = wn * 32 + nt * 8 + 2 * fs;
            float2 v0 = make_float2(acc[mt][nt][0] * inv0, acc[mt][nt][1] * inv0);
            float2 v1 = make_float2(acc[mt][nt][2] * inv1, acc[mt][nt][3] * inv1);
            *(float2*)&op0[col] = v0;
            *(float2*)&op1[col] = v1;
        }
    }
}

// ---------------------------------------------------------------------------
extern "C" void kernel_launch(void* const* d_in, const int* in_sizes, int n_in,
                              void* d_out, int out_size) {
    const float* x  = (const float*)d_in[0];
    const float* W1 = (const float*)d_in[1];
    const float* W2 = (const float*)d_in[2];
    float* out = (float*)d_out;

    static bool attr_set = false;
    if (!attr_set) {
        cudaFuncSetAttribute(k3_attn_mma, cudaFuncAttributeMaxDynamicSharedMemorySize, SMEM_K3);
        attr_set = true;
    }

    k1_proj<<<(NB * NA) / 32, 256>>>(x, W1, W2);
    k3_attn_mma<<<dim3(NA / 128, ND / 128, NB), 256, SMEM_K3>>>(x, out);
}

// round 6
// speedup vs baseline: 4.0903x; 1.2561x over previous
#include <cuda_runtime.h>
#include <cuda_fp16.h>
#include <cstdint>
#include <math.h>

#define NB 16
#define NA 2048
#define ND 512
#define NR 10
#define INV_SQRT_DK 0.04419417382415922f  // 1/sqrt(512)

// Scratch (no device allocations allowed)
__device__ float g_left[(size_t)NB * NA * NR];    // left proj, pre-scaled by 1/sqrt(dk)
__device__ float g_rightT[(size_t)NB * NA * NR];  // right proj, [b][c][r]

__device__ __forceinline__ uint32_t smem_u32(const void* p) {
    uint32_t a;
    asm("{ .reg .u64 t; cvta.to.shared.u64 t, %1; cvt.u32.u64 %0, t; }" : "=r"(a) : "l"(p));
    return a;
}
__device__ __forceinline__ void cp_async16(uint32_t saddr, const void* gptr) {
    asm volatile("cp.async.cg.shared.global [%0], [%1], 16;" :: "r"(saddr), "l"(gptr) : "memory");
}
#define CP_COMMIT() asm volatile("cp.async.commit_group;" ::: "memory")
#define CP_WAIT1()  asm volatile("cp.async.wait_group 1;" ::: "memory")

__device__ __forceinline__ void mma_f16(float* d, const uint32_t* a, const uint32_t* bfr) {
    asm volatile(
        "mma.sync.aligned.m16n8k16.row.col.f32.f16.f16.f32 "
        "{%0,%1,%2,%3}, {%4,%5,%6,%7}, {%8,%9}, {%0,%1,%2,%3};"
        : "+f"(d[0]), "+f"(d[1]), "+f"(d[2]), "+f"(d[3])
        : "r"(a[0]), "r"(a[1]), "r"(a[2]), "r"(a[3]), "r"(bfr[0]), "r"(bfr[1]));
}
__device__ __forceinline__ uint32_t pack_h2(float lo, float hi) {
    uint32_t u;
    asm("cvt.rn.f16x2.f32 %0, %1, %2;" : "=r"(u) : "f"(hi), "f"(lo));  // lo -> .x
    return u;
}

// ===========================================================================
// K1: projections. 4 rows per warp to amortize W smem reads.
// ===========================================================================
__global__ void __launch_bounds__(256)
k1_proj(const float* __restrict__ x, const float* __restrict__ W1,
        const float* __restrict__ W2) {
    __shared__ float W1T[NR][ND];
    __shared__ float W2s[NR][ND];
    int tid = threadIdx.x;
    for (int idx = tid; idx < ND * NR; idx += 256) {
        int d = idx / NR, r = idx % NR;
        W1T[r][d] = W1[idx];               // W1 [D, R], r fastest
    }
    for (int idx = tid; idx < NR * ND; idx += 256) {
        W2s[idx / ND][idx % ND] = W2[idx]; // W2 [R, D], d fastest
    }
    __syncthreads();

    int warp = tid >> 5, lane = tid & 31;
    int row0 = blockIdx.x * 32 + warp * 4;
    const float* xr0 = x + (size_t)row0 * ND;

    float accL[4][NR], accR[4][NR];
#pragma unroll
    for (int i = 0; i < 4; i++)
#pragma unroll
        for (int r = 0; r < NR; r++) { accL[i][r] = 0.f; accR[i][r] = 0.f; }

#pragma unroll
    for (int k = 0; k < ND / 32; k++) {
        int d = lane + 32 * k;
        float xv[4];
#pragma unroll
        for (int i = 0; i < 4; i++) xv[i] = xr0[(size_t)i * ND + d];
#pragma unroll
        for (int r = 0; r < NR; r++) {
            float w1 = W1T[r][d];
            float w2 = W2s[r][d];
#pragma unroll
            for (int i = 0; i < 4; i++) {
                accL[i][r] += xv[i] * w1;
                accR[i][r] += xv[i] * w2;
            }
        }
    }
#pragma unroll
    for (int i = 0; i < 4; i++)
#pragma unroll
        for (int r = 0; r < NR; r++) {
#pragma unroll
            for (int off = 16; off; off >>= 1) {
                accL[i][r] += __shfl_down_sync(0xffffffffu, accL[i][r], off);
                accR[i][r] += __shfl_down_sync(0xffffffffu, accR[i][r], off);
            }
        }
    if (lane == 0) {
#pragma unroll
        for (int i = 0; i < 4; i++) {
            float* lp = g_left   + (size_t)(row0 + i) * NR;
            float* rp = g_rightT + (size_t)(row0 + i) * NR;
#pragma unroll
            for (int r = 0; r < NR; r++) {
                lp[r] = accL[i][r] * INV_SQRT_DK;
                rp[r] = accR[i][r];
            }
        }
    }
}

// ===========================================================================
// K3: fp16 warp-MMA (m16n8k16) attention-weighted sum, cp.async pipelined.
//   CTA: M=128 queries x N=256 d-cols, 512 threads (16 warps = 2m x 8n,
//   warp tile 64x32). K-loop 2048 keys, KC=32 (2 k16 steps).
//   As: exp-scores half2 k-paired [128 m][20 words] (16 used + pad 4).
//   Bs: raw f32 x, cp.async, double-buffered [2][32][260].
//   Bh: x as half2 k-paired [16 k2][264 words] (256 used + pad 8),
//       converted from Bs each chunk.
//   Unnormalized accumulation; per-row denominator in regs -> epilogue.
// ===========================================================================
#define KC 32
#define NCHUNK (NA / KC)
#define BS_STRIDE 260
#define BS_CHUNK (KC * BS_STRIDE)        // 8320 floats
#define BH_STRIDE 264
// dynamic smem layout (bytes)
#define OFF_AS 0                          // 128*20*4      = 10240
#define OFF_BH 10240                      // 16*264*4      = 16896
#define OFF_BS 27136                      // 2*8320*4      = 66560
#define OFF_RT 93696                      // 2*10*32*4     = 2560
#define OFF_SL 96256                      // 128*4         = 512
#define SMEM_K3 96768

__global__ void __launch_bounds__(512, 1)
k3_attn_mma(const float* __restrict__ x, float* __restrict__ out) {
    extern __shared__ char smem[];
    uint32_t* As  = (uint32_t*)(smem + OFF_AS);   // [128][20] half2 words
    uint32_t* Bh  = (uint32_t*)(smem + OFF_BH);   // [16][264] half2 words
    float*    Bsf = (float*)(smem + OFF_BS);      // [2][32][260]
    float*    RtT = (float*)(smem + OFF_RT);      // [2][10][32]
    float*    sl  = (float*)(smem + OFF_SL);      // [128]
    uint32_t  sb  = smem_u32(smem);

    int tid = threadIdx.x;
    int wid = tid >> 5, lane = tid & 31;
    int b  = blockIdx.z;
    int a0 = blockIdx.x * 128;
    int n0 = blockIdx.y * 256;

    // score-gen mapping: 1 row x 8 k per thread
    int mg = tid >> 2, kg = tid & 3;
    float ls[NR];
    {
        const float* lp = g_left + ((size_t)b * NA + a0 + mg) * NR;
#pragma unroll
        for (int r = 0; r < NR; r++) ls[r] = lp[r];
    }
    float lacc = 0.f;

    // MMA mapping: 16 warps = 2(m) x 8(n)
    int wm = wid >> 3, wn = wid & 7;
    int fs = lane & 3, fq = lane >> 2;
    float acc[4][4][4];
#pragma unroll
    for (int mt = 0; mt < 4; mt++)
#pragma unroll
        for (int nt = 0; nt < 4; nt++)
#pragma unroll
            for (int q = 0; q < 4; q++) acc[mt][nt][q] = 0.f;

    const float* xb = x + (size_t)b * NA * ND;

    // ---- prologue: prefetch B[0] (f32), RtT[0] ----
#pragma unroll
    for (int it = 0; it < 4; it++) {
        int u = tid + 512 * it;            // 2048 float4 units
        int kk = u >> 6, f4 = u & 63;
        uint32_t dst = sb + OFF_BS + (uint32_t)(kk * BS_STRIDE + 4 * f4) * 4;
        cp_async16(dst, xb + (size_t)kk * ND + n0 + 4 * f4);
    }
    CP_COMMIT();
    if (tid < KC * NR) {
        int k = tid / NR, r = tid % NR;
        RtT[r * 32 + k] = g_rightT[((size_t)b * NA + k) * NR + r];
    }

    for (int c = 0; c < NCHUNK; c++) {
        int buf = c & 1;

        // prefetch B[c+1] into the other buffer (its last reader finished
        // before the previous chunk's MMA barrier)
        if (c + 1 < NCHUNK) {
            int pb = (c + 1) & 1;
#pragma unroll
            for (int it = 0; it < 4; it++) {
                int u = tid + 512 * it;
                int kk = u >> 6, f4 = u & 63;
                uint32_t dst = sb + OFF_BS + (uint32_t)(pb * BS_CHUNK + kk * BS_STRIDE + 4 * f4) * 4;
                cp_async16(dst, xb + (size_t)((c + 1) * KC + kk) * ND + n0 + 4 * f4);
            }
        }
        CP_COMMIT();       // one group per iter keeps wait_group math fixed
        CP_WAIT1();        // B[c] landed
        __syncthreads();   // B[c] visible; Bh/As free (prev MMA done)

        // prefetch RtT for chunk c+1
        if (c + 1 < NCHUNK && tid < KC * NR) {
            float* rtw = RtT + ((c + 1) & 1) * (NR * 32);
            int k = tid / NR, r = tid % NR;
            rtw[r * 32 + k] = g_rightT[((size_t)b * NA + (c + 1) * KC + k) * NR + r];
        }

        // ---- convert B f32 -> half2 k-paired ----
        {
            const float* Bc = Bsf + buf * BS_CHUNK;
#pragma unroll
            for (int it = 0; it < 2; it++) {
                int v = tid + 512 * it;        // 1024 uint4 units
                int k2 = v >> 6, n4 = v & 63;
                float4 f0 = *(const float4*)&Bc[(2 * k2) * BS_STRIDE + 4 * n4];
                float4 f1 = *(const float4*)&Bc[(2 * k2 + 1) * BS_STRIDE + 4 * n4];
                uint4 h;
                h.x = pack_h2(f0.x, f1.x);
                h.y = pack_h2(f0.y, f1.y);
                h.z = pack_h2(f0.z, f1.z);
                h.w = pack_h2(f0.w, f1.w);
                *(uint4*)&Bh[k2 * BH_STRIDE + 4 * n4] = h;
            }
        }

        // ---- score-gen: P' = exp(score) -> half2 into As ----
        {
            const float* rt = RtT + (c & 1) * (NR * 32);
            float sc[8];
#pragma unroll
            for (int j = 0; j < 8; j++) sc[j] = 0.f;
#pragma unroll
            for (int r = 0; r < NR; r++) {
                float4 rt0 = *(const float4*)&rt[r * 32 + 8 * kg];
                float4 rt1 = *(const float4*)&rt[r * 32 + 8 * kg + 4];
                float lv = ls[r];
                sc[0] += lv * rt0.x; sc[1] += lv * rt0.y;
                sc[2] += lv * rt0.z; sc[3] += lv * rt0.w;
                sc[4] += lv * rt1.x; sc[5] += lv * rt1.y;
                sc[6] += lv * rt1.z; sc[7] += lv * rt1.w;
            }
            float e[8];
            float s = 0.f;
#pragma unroll
            for (int j = 0; j < 8; j++) { e[j] = __expf(sc[j]); s += e[j]; }
            lacc += s;
            uint4 t;
            t.x = pack_h2(e[0], e[1]);
            t.y = pack_h2(e[2], e[3]);
            t.z = pack_h2(e[4], e[5]);
            t.w = pack_h2(e[6], e[7]);
            *(uint4*)&As[mg * 20 + 4 * kg] = t;
        }
        __syncthreads();   // As, Bh staged

        // ---- MMAs: 2 k16 steps x 4 m x 4 n ----
#pragma unroll
        for (int ks = 0; ks < 2; ks++) {
            uint32_t afr[4][4], bfr[4][2];
            int arow = wm * 64 + fq;
            int acol = ks * 8 + fs;
#pragma unroll
            for (int mt = 0; mt < 4; mt++) {
                afr[mt][0] = As[(arow + mt * 16) * 20 + acol];
                afr[mt][1] = As[(arow + mt * 16 + 8) * 20 + acol];
                afr[mt][2] = As[(arow + mt * 16) * 20 + acol + 4];
                afr[mt][3] = As[(arow + mt * 16 + 8) * 20 + acol + 4];
            }
            int bk = ks * 8 + fs;
            int bcol = wn * 32 + fq;
#pragma unroll
            for (int nt = 0; nt < 4; nt++) {
                bfr[nt][0] = Bh[bk * BH_STRIDE + bcol + nt * 8];
                bfr[nt][1] = Bh[(bk + 4) * BH_STRIDE + bcol + nt * 8];
            }
#pragma unroll
            for (int mt = 0; mt < 4; mt++)
#pragma unroll
                for (int nt = 0; nt < 4; nt++)
                    mma_f16(acc[mt][nt], afr[mt], bfr[nt]);
        }
    }

    // ---- softmax denominators: reduce over the 4 kg threads ----
    lacc += __shfl_xor_sync(0xffffffffu, lacc, 1);
    lacc += __shfl_xor_sync(0xffffffffu, lacc, 2);
    if (kg == 0) sl[mg] = lacc;
    __syncthreads();

    // ---- epilogue: normalize + store ----
#pragma unroll
    for (int mt = 0; mt < 4; mt++) {
        int r0 = wm * 64 + mt * 16 + fq;
        int r1 = r0 + 8;
        float inv0 = 1.0f / sl[r0];
        float inv1 = 1.0f / sl[r1];
        float* op0 = out + ((size_t)b * NA + a0 + r0) * ND + n0;
        float* op1 = out + ((size_t)b * NA + a0 + r1) * ND + n0;
#pragma unroll
        for (int nt = 0; nt < 4; nt++) {
            int col = wn * 32 + nt * 8 + 2 * fs;
            float2 v0 = make_float2(acc[mt][nt][0] * inv0, acc[mt][nt][1] * inv0);
            float2 v1 = make_float2(acc[mt][nt][2] * inv1, acc[mt][nt][3] * inv1);
            *(float2*)&op0[col] = v0;
            *(float2*)&op1[col] = v1;
        }
    }
}

// ---------------------------------------------------------------------------
extern "C" void kernel_launch(void* const* d_in, const int* in_sizes, int n_in,
                              void* d_out, int out_size) {
    const float* x  = (const float*)d_in[0];
    const float* W1 = (const float*)d_in[1];
    const float* W2 = (const float*)d_in[2];
    float* out = (float*)d_out;

    static bool attr_set = false;
    if (!attr_set) {
        cudaFuncSetAttribute(k3_attn_mma, cudaFuncAttributeMaxDynamicSharedMemorySize, SMEM_K3);
        attr_set = true;
    }

    k1_proj<<<(NB * NA) / 32, 256>>>(x, W1, W2);
    k3_attn_mma<<<dim3(NA / 128, ND / 256, NB), 512, SMEM_K3>>>(x, out);
}